// round 11
// baseline (speedup 1.0000x reference)
#include <cuda_runtime.h>
#include <cstdint>

#define NB   2048
#define NTOK 64
#define CDIM 512
#define NH   8
#define HD   64

#define SQ 68   // smem row stride (floats) for q1/q2/k1/attn tiles
#define SV 72   // smem row stride (floats) for v tile

#define TPC  8                               // tiles per CTA (pipelined)

#define OFF_Q1  0
#define OFF_Q2  (NTOK * SQ)
#define OFF_K1  (2 * NTOK * SQ)
#define OFF_ATS (3 * NTOK * SQ)              // dedicated mixed-attn tile
#define OFF_V   (4 * NTOK * SQ)
#define BUFF    (4 * NTOK * SQ + NTOK * SV)  // 22016 floats = 88064 B -> 2 CTAs/SM

// Precomputed bias[h][n][m] = bias_table[rel_index[n,m], h] * log2(e)
__device__ float g_bias[NH * NTOK * NTOK];

__global__ void bias_precompute(const float* __restrict__ bias_table,
                                const int* __restrict__ rel_index) {
    int i = blockIdx.x * blockDim.x + threadIdx.x;
    if (i < NTOK * NTOK) {
        int ri = rel_index[i];
#pragma unroll
        for (int h = 0; h < NH; h++)
            g_bias[h * (NTOK * NTOK) + i] = bias_table[ri * NH + h] * 1.4426950408889634f;
    }
}

__device__ __forceinline__ float ex2(float x) {
    float y;
    asm("ex2.approx.ftz.f32 %0, %1;" : "=f"(y) : "f"(x));
    return y;
}

__device__ __forceinline__ float tf32r(float x) {
    uint32_t u;
    asm("cvt.rna.tf32.f32 %0, %1;" : "=r"(u) : "f"(x));
    return __uint_as_float(u);
}
__device__ __forceinline__ uint32_t tf32u(float x) {
    uint32_t u;
    asm("cvt.rna.tf32.f32 %0, %1;" : "=r"(u) : "f"(x));
    return u;
}
__device__ __forceinline__ uint32_t tf32b(uint32_t x) {
    uint32_t u;
    asm("cvt.rna.tf32.f32 %0, %1;" : "=r"(u) : "f"(__uint_as_float(x)));
    return u;
}

__device__ __forceinline__ void ldsm4(uint32_t r[4], uint32_t addr) {
    asm volatile("ldmatrix.sync.aligned.m8n8.x4.shared.b16 {%0,%1,%2,%3}, [%4];\n"
                 : "=r"(r[0]), "=r"(r[1]), "=r"(r[2]), "=r"(r[3]) : "r"(addr));
}

__device__ __forceinline__ void mma_tf32(float c[4],
                                         uint32_t a0, uint32_t a1, uint32_t a2, uint32_t a3,
                                         uint32_t b0, uint32_t b1) {
    asm volatile(
        "mma.sync.aligned.m16n8k8.row.col.f32.tf32.tf32.f32 "
        "{%0,%1,%2,%3}, {%4,%5,%6,%7}, {%8,%9}, {%0,%1,%2,%3};\n"
        : "+f"(c[0]), "+f"(c[1]), "+f"(c[2]), "+f"(c[3])
        : "r"(a0), "r"(a1), "r"(a2), "r"(a3), "r"(b0), "r"(b1));
}

__device__ __forceinline__ void cpa16(uint32_t s, const float* g) {
    asm volatile("cp.async.cg.shared.global [%0], [%1], 16;\n" :: "r"(s), "l"(g));
}
__device__ __forceinline__ void cpcommit() {
    asm volatile("cp.async.commit_group;\n");
}
template <int N>
__device__ __forceinline__ void cpwait() {
    asm volatile("cp.async.wait_group %0;\n" :: "n"(N));
}

extern __shared__ float smem[];

__global__ __launch_bounds__(128)
void win_attn_kernel(const float* __restrict__ q1g,
                     const float* __restrict__ q2g,
                     const float* __restrict__ k1g,
                     const float* __restrict__ v1g,
                     const float* __restrict__ gating,
                     float* __restrict__ outg) {
    const int tid  = threadIdx.x;
    const int lane = tid & 31;
    const int warp = tid >> 5;
    const int qg = lane >> 2;   // group id (0..7)
    const int qc = lane & 3;    // thread-in-group (0..3)
    const uint32_t sb = (uint32_t)__cvta_generic_to_shared(smem);

    float* ats = smem + OFF_ATS;
    float* vs  = smem + OFF_V;

    const int tile0 = blockIdx.x * TPC;

    // per-thread staging coordinates (fixed across tiles)
    const int row_lo = warp * 16 + qg;
    const int row_hi = row_lo + 8;
    const int a_row = warp * 16 + (lane & 15);
    const uint32_t a_coff = (uint32_t)((lane >> 4) << 4);           // 0 or 16 bytes
    const int b_row_in = ((lane >> 4) << 3) + (lane & 7);           // 0..15
    const uint32_t b_coff = (uint32_t)(((lane >> 3) & 1) << 4);     // 0 or 16 bytes

    auto issue_qk = [&](int tile) {
        const int b = tile >> 3, h = tile & 7;
        const size_t base = (size_t)b * NTOK * CDIM + (size_t)h * HD;
#pragma unroll
        for (int it = 0; it < 8; it++) {
            const int i  = tid + it * 128;
            const int r  = i >> 4;
            const int c4 = (i & 15) << 2;
            const size_t go = base + (size_t)r * CDIM + c4;
            cpa16(sb + (uint32_t)(OFF_Q1 + r * SQ + c4) * 4u, q1g + go);
            cpa16(sb + (uint32_t)(OFF_Q2 + r * SQ + c4) * 4u, q2g + go);
            cpa16(sb + (uint32_t)(OFF_K1 + r * SQ + c4) * 4u, k1g + go);
        }
        cpcommit();
    };
    auto issue_v = [&](int tile) {
        const int b = tile >> 3, h = tile & 7;
        const size_t base = (size_t)b * NTOK * CDIM + (size_t)h * HD;
#pragma unroll
        for (int it = 0; it < 8; it++) {
            const int i  = tid + it * 128;
            const int r  = i >> 4;
            const int c4 = (i & 15) << 2;
            cpa16(sb + (uint32_t)(OFF_V + r * SV + c4) * 4u,
                  v1g + base + (size_t)r * CDIM + c4);
        }
        cpcommit();
    };

    issue_qk(tile0);   // group: qk(0)
    issue_v(tile0);    // group: v(0)

    for (int t = 0; t < TPC; t++) {
        const int tile = tile0 + t;
        const int b = tile >> 3, h = tile & 7;

        // ---- bias + gating prefetch (free: overlaps the qk wait) ----
        float2 blo[8], bhi[8];
        {
            const float* bp_lo = g_bias + h * (NTOK * NTOK) + row_lo * NTOK + 2 * qc;
            const float* bp_hi = g_bias + h * (NTOK * NTOK) + row_hi * NTOK + 2 * qc;
#pragma unroll
            for (int n = 0; n < 8; n++) {
                blo[n] = *(const float2*)(bp_lo + n * 8);
                bhi[n] = *(const float2*)(bp_hi + n * 8);
            }
        }
        const float gp = __ldg(gating + h);
        const float gv = 1.0f / (1.0f + __expf(-gp));

        // qk(t) landed (v(t) may still be pending)
        cpwait<1>();
        __syncthreads();

        // ---- QK^T for both maps (ldmatrix + register RNA-cvt) ----
        uint32_t adQ1 = sb + (uint32_t)(OFF_Q1 + a_row * SQ) * 4u + a_coff;
        uint32_t adQ2 = sb + (uint32_t)(OFF_Q2 + a_row * SQ) * 4u + a_coff;
        uint32_t adB[4];
#pragma unroll
        for (int j = 0; j < 4; j++)
            adB[j] = sb + (uint32_t)(OFF_K1 + (16 * j + b_row_in) * SQ) * 4u + b_coff;

        float C1[8][4], C2[8][4];
#pragma unroll
        for (int n = 0; n < 8; n++)
#pragma unroll
            for (int j = 0; j < 4; j++) { C1[n][j] = 0.f; C2[n][j] = 0.f; }

#pragma unroll
        for (int kk = 0; kk < 8; kk++) {
            uint32_t A1[4], A2[4], B[4][4];
            ldsm4(A1, adQ1);  adQ1 += 32;
            ldsm4(A2, adQ2);  adQ2 += 32;
#pragma unroll
            for (int j = 0; j < 4; j++) { ldsm4(B[j], adB[j]); adB[j] += 32; }
#pragma unroll
            for (int i = 0; i < 4; i++) {
                A1[i] = tf32b(A1[i]);
                A2[i] = tf32b(A2[i]);
#pragma unroll
                for (int j = 0; j < 4; j++) B[j][i] = tf32b(B[j][i]);
            }
#pragma unroll
            for (int n = 0; n < 8; n++) {
                const uint32_t b0 = B[n >> 1][(n & 1) * 2];
                const uint32_t b1 = B[n >> 1][(n & 1) * 2 + 1];
                mma_tf32(C1[n], A1[0], A1[1], A1[2], A1[3], b0, b1);
                mma_tf32(C2[n], A2[0], A2[1], A2[2], A2[3], b0, b1);
            }
        }

        // ---- q1/q2/k1 dead: prefetch next tile's QK operands under softmax+AV ----
        __syncthreads();
        if (t + 1 < TPC) issue_qk(tile + 1);     // group: qk(t+1)

        // ---- scale+bias in log2 domain ----
        const float SCL = 0.18033688011112042f;  // 0.125 * log2(e)
#pragma unroll
        for (int n = 0; n < 8; n++) {
            C1[n][0] = C1[n][0] * SCL + blo[n].x;
            C1[n][1] = C1[n][1] * SCL + blo[n].y;
            C1[n][2] = C1[n][2] * SCL + bhi[n].x;
            C1[n][3] = C1[n][3] * SCL + bhi[n].y;
            C2[n][0] = C2[n][0] * SCL + blo[n].x;
            C2[n][1] = C2[n][1] * SCL + blo[n].y;
            C2[n][2] = C2[n][2] * SCL + bhi[n].x;
            C2[n][3] = C2[n][3] * SCL + bhi[n].y;
        }

        // ---- dual softmax via ex2.approx (args bounded ~|9|, no max pass) ----
        float s1l = 0.f, s1h = 0.f, s2l = 0.f, s2h = 0.f;
#pragma unroll
        for (int n = 0; n < 8; n++) {
            C1[n][0] = ex2(C1[n][0]); s1l += C1[n][0];
            C1[n][1] = ex2(C1[n][1]); s1l += C1[n][1];
            C1[n][2] = ex2(C1[n][2]); s1h += C1[n][2];
            C1[n][3] = ex2(C1[n][3]); s1h += C1[n][3];
            C2[n][0] = ex2(C2[n][0]); s2l += C2[n][0];
            C2[n][1] = ex2(C2[n][1]); s2l += C2[n][1];
            C2[n][2] = ex2(C2[n][2]); s2h += C2[n][2];
            C2[n][3] = ex2(C2[n][3]); s2h += C2[n][3];
        }
#pragma unroll
        for (int off = 1; off <= 2; off <<= 1) {
            s1l += __shfl_xor_sync(0xffffffffu, s1l, off);
            s1h += __shfl_xor_sync(0xffffffffu, s1h, off);
            s2l += __shfl_xor_sync(0xffffffffu, s2l, off);
            s2h += __shfl_xor_sync(0xffffffffu, s2h, off);
        }

        const float w1l = (1.0f - gv) / s1l, w1h = (1.0f - gv) / s1h;
        const float w2l = gv / s2l,          w2h = gv / s2h;

        // mixed attention -> warp-private rows of the dedicated ats tile
#pragma unroll
        for (int n = 0; n < 8; n++) {
            float2 lo, hi;
            lo.x = tf32r(C1[n][0] * w1l + C2[n][0] * w2l);
            lo.y = tf32r(C1[n][1] * w1l + C2[n][1] * w2l);
            hi.x = tf32r(C1[n][2] * w1h + C2[n][2] * w2h);
            hi.y = tf32r(C1[n][3] * w1h + C2[n][3] * w2h);
            *(float2*)&ats[row_lo * SQ + n * 8 + 2 * qc] = lo;
            *(float2*)&ats[row_hi * SQ + n * 8 + 2 * qc] = hi;
        }
        __syncwarp();

        // ---- v(t) landed (its latency hid under QK+softmax) ----
        if (t + 1 < TPC) cpwait<1>();   // allow qk(t+1) pending
        else             cpwait<0>();
        __syncthreads();

        // ---- O = attn @ V ----
        float O[8][4];
#pragma unroll
        for (int n = 0; n < 8; n++)
#pragma unroll
            for (int j = 0; j < 4; j++) O[n][j] = 0.f;

        uint32_t adA = sb + (uint32_t)(OFF_ATS + a_row * SQ) * 4u + a_coff;
#pragma unroll
        for (int kk = 0; kk < 8; kk++) {
            const int k0 = kk * 8;
            uint32_t AF[4];
            ldsm4(AF, adA);  adA += 32;   // already tf32 values
#pragma unroll
            for (int n = 0; n < 8; n++) {
                const int dcol = n * 8 + qg;
                uint32_t b0 = tf32u(vs[(k0 + qc) * SV + dcol]);
                uint32_t b1 = tf32u(vs[(k0 + qc + 4) * SV + dcol]);
                mma_tf32(O[n], AF[0], AF[1], AF[2], AF[3], b0, b1);
            }
        }

        // ---- v region dead: prefetch next tile's v under the epilogue ----
        __syncthreads();
        if (t + 1 < TPC) issue_v(tile + 1);      // group: v(t+1)

        // ---- store output: out[b, row, h*64 + d] ----
        float* op = outg + (size_t)b * NTOK * CDIM + (size_t)h * HD;
#pragma unroll
        for (int n = 0; n < 8; n++) {
            const int dcol = n * 8 + 2 * qc;
            *(float2*)&op[(size_t)row_lo * CDIM + dcol] = make_float2(O[n][0], O[n][1]);
            *(float2*)&op[(size_t)row_hi * CDIM + dcol] = make_float2(O[n][2], O[n][3]);
        }
    }
}

extern "C" void kernel_launch(void* const* d_in, const int* in_sizes, int n_in,
                              void* d_out, int out_size) {
    const float* q1 = (const float*)d_in[0];
    const float* q2 = (const float*)d_in[1];
    const float* k1 = (const float*)d_in[2];
    const float* v1 = (const float*)d_in[3];
    // d_in[4] = k2 (unused by the reference math)
    const float* bias_table = (const float*)d_in[5];
    const float* gating     = (const float*)d_in[6];
    const int*   rel_index  = (const int*)d_in[7];
    float* out = (float*)d_out;

    bias_precompute<<<16, 256>>>(bias_table, rel_index);

    const int smem_bytes = BUFF * (int)sizeof(float);  // 88064
    cudaFuncSetAttribute(win_attn_kernel,
                         cudaFuncAttributeMaxDynamicSharedMemorySize, smem_bytes);
    win_attn_kernel<<<(NB * NH) / TPC, 128, smem_bytes>>>(q1, q2, k1, v1, gating, out);
}

// round 13
// speedup vs baseline: 1.0737x; 1.0737x over previous
#include <cuda_runtime.h>
#include <cstdint>

#define NB   2048
#define NTOK 64
#define CDIM 512
#define NH   8
#define HD   64

#define SQ 68   // smem row stride (floats) for q1/q2/k1/attn tiles
#define SV 72   // smem row stride (floats) for v tile

#define OFF_Q1 0
#define OFF_Q2 (NTOK * SQ)
#define OFF_K1 (2 * NTOK * SQ)
#define OFF_V  (3 * NTOK * SQ)
#define BUFF   (3 * NTOK * SQ + NTOK * SV)   // 17664 floats = 70656 B -> 3 CTAs/SM

__device__ __forceinline__ float ex2(float x) {
    float y;
    asm("ex2.approx.ftz.f32 %0, %1;" : "=f"(y) : "f"(x));
    return y;
}

__device__ __forceinline__ float tf32r(float x) {
    uint32_t u;
    asm("cvt.rna.tf32.f32 %0, %1;" : "=r"(u) : "f"(x));
    return __uint_as_float(u);
}
__device__ __forceinline__ uint32_t tf32b(uint32_t x) {
    uint32_t u;
    asm("cvt.rna.tf32.f32 %0, %1;" : "=r"(u) : "f"(__uint_as_float(x)));
    return u;
}

__device__ __forceinline__ void ldsm4(uint32_t r[4], uint32_t addr) {
    asm volatile("ldmatrix.sync.aligned.m8n8.x4.shared.b16 {%0,%1,%2,%3}, [%4];\n"
                 : "=r"(r[0]), "=r"(r[1]), "=r"(r[2]), "=r"(r[3]) : "r"(addr));
}

__device__ __forceinline__ void mma_tf32(float c[4],
                                         uint32_t a0, uint32_t a1, uint32_t a2, uint32_t a3,
                                         uint32_t b0, uint32_t b1) {
    asm volatile(
        "mma.sync.aligned.m16n8k8.row.col.f32.tf32.tf32.f32 "
        "{%0,%1,%2,%3}, {%4,%5,%6,%7}, {%8,%9}, {%0,%1,%2,%3};\n"
        : "+f"(c[0]), "+f"(c[1]), "+f"(c[2]), "+f"(c[3])
        : "r"(a0), "r"(a1), "r"(a2), "r"(a3), "r"(b0), "r"(b1));
}

__device__ __forceinline__ void cpa16(uint32_t s, const float* g) {
    asm volatile("cp.async.cg.shared.global [%0], [%1], 16;\n" :: "r"(s), "l"(g));
}

extern __shared__ float smem[];

__global__ __launch_bounds__(128)
void win_attn_kernel(const float* __restrict__ q1g,
                     const float* __restrict__ q2g,
                     const float* __restrict__ k1g,
                     const float* __restrict__ v1g,
                     const float* __restrict__ bias_table,
                     const float* __restrict__ gating,
                     const int* __restrict__ rel_index,
                     float* __restrict__ outg) {
    const int bh = blockIdx.x;
    const int b  = bh >> 3;
    const int h  = bh & 7;
    const int tid  = threadIdx.x;
    const int lane = tid & 31;
    const int warp = tid >> 5;
    const int qg = lane >> 2;   // group id (0..7)
    const int qc = lane & 3;    // thread-in-group (0..3)
    const uint32_t sb = (uint32_t)__cvta_generic_to_shared(smem);

    float* vs  = smem + OFF_V;
    float* ats = smem + OFF_Q1;   // q1 raw early; mixed attn later (warp-private rows)

    // ---- async stage: group 0 = q1+q2+k1 (QK path), group 1 = v (AV path) ----
    const size_t base = (size_t)b * NTOK * CDIM + (size_t)h * HD;
#pragma unroll
    for (int it = 0; it < 8; it++) {
        const int i  = tid + it * 128;
        const int r  = i >> 4;
        const int c4 = (i & 15) << 2;
        const size_t go = base + (size_t)r * CDIM + c4;
        cpa16(sb + (uint32_t)(OFF_Q1 + r * SQ + c4) * 4u, q1g + go);
        cpa16(sb + (uint32_t)(OFF_Q2 + r * SQ + c4) * 4u, q2g + go);
        cpa16(sb + (uint32_t)(OFF_K1 + r * SQ + c4) * 4u, k1g + go);
    }
    asm volatile("cp.async.commit_group;\n");
#pragma unroll
    for (int it = 0; it < 8; it++) {
        const int i  = tid + it * 128;
        const int r  = i >> 4;
        const int c4 = (i & 15) << 2;
        cpa16(sb + (uint32_t)(OFF_V + r * SV + c4) * 4u,
              v1g + base + (size_t)r * CDIM + c4);
    }
    asm volatile("cp.async.commit_group;\n");

    const int row_lo = warp * 16 + qg;
    const int row_hi = row_lo + 8;

    // ---- ldmatrix lane addressing (32-bit words via b16 tiles) ----
    const int a_row = warp * 16 + (lane & 15);
    const uint32_t a_coff = (uint32_t)((lane >> 4) << 4);           // 0 or 16 bytes
    uint32_t adQ1 = sb + (uint32_t)(OFF_Q1 + a_row * SQ) * 4u + a_coff;
    uint32_t adQ2 = sb + (uint32_t)(OFF_Q2 + a_row * SQ) * 4u + a_coff;
    const int b_row_in = ((lane >> 4) << 3) + (lane & 7);           // 0..15
    const uint32_t b_coff = (uint32_t)(((lane >> 3) & 1) << 4);     // 0 or 16 bytes
    uint32_t adB[4];
#pragma unroll
    for (int j = 0; j < 4; j++)
        adB[j] = sb + (uint32_t)(OFF_K1 + (16 * j + b_row_in) * SQ) * 4u + b_coff;

    // ---- bias gather + gating (free: hides under the cp.async DRAM wait) ----
    const float LOG2E = 1.4426950408889634f;
    float2 blo[8], bhi[8];
    {
        const int* ri_lo = rel_index + row_lo * NTOK + 2 * qc;
        const int* ri_hi = rel_index + row_hi * NTOK + 2 * qc;
#pragma unroll
        for (int n = 0; n < 8; n++) {
            int2 i0 = *(const int2*)(ri_lo + n * 8);
            int2 i1 = *(const int2*)(ri_hi + n * 8);
            blo[n].x = bias_table[i0.x * NH + h] * LOG2E;
            blo[n].y = bias_table[i0.y * NH + h] * LOG2E;
            bhi[n].x = bias_table[i1.x * NH + h] * LOG2E;
            bhi[n].y = bias_table[i1.y * NH + h] * LOG2E;
        }
    }
    const float gp = __ldg(gating + h);
    const float gv = 1.0f / (1.0f + __expf(-gp));

    // ---- QK path operands landed ----
    asm volatile("cp.async.wait_group 1;\n");
    __syncthreads();

    // ---- QK^T for both maps (raw frags via ldmatrix, RNA-cvt in registers) ----
    float C1[8][4], C2[8][4];
#pragma unroll
    for (int n = 0; n < 8; n++)
#pragma unroll
        for (int j = 0; j < 4; j++) { C1[n][j] = 0.f; C2[n][j] = 0.f; }

#pragma unroll
    for (int kk = 0; kk < 8; kk++) {
        uint32_t A1[4], A2[4], B[4][4];
        ldsm4(A1, adQ1);  adQ1 += 32;
        ldsm4(A2, adQ2);  adQ2 += 32;
#pragma unroll
        for (int j = 0; j < 4; j++) { ldsm4(B[j], adB[j]); adB[j] += 32; }
#pragma unroll
        for (int i = 0; i < 4; i++) {
            A1[i] = tf32b(A1[i]);
            A2[i] = tf32b(A2[i]);
#pragma unroll
            for (int j = 0; j < 4; j++) B[j][i] = tf32b(B[j][i]);
        }
#pragma unroll
        for (int n = 0; n < 8; n++) {
            const uint32_t b0 = B[n >> 1][(n & 1) * 2];
            const uint32_t b1 = B[n >> 1][(n & 1) * 2 + 1];
            mma_tf32(C1[n], A1[0], A1[1], A1[2], A1[3], b0, b1);
            mma_tf32(C2[n], A2[0], A2[1], A2[2], A2[3], b0, b1);
        }
    }

    // ---- scale+bias in log2 domain: y = C*(0.125*log2e) + bias*log2e ----
    const float SCL = 0.18033688011112042f;  // 0.125 * log2(e)
#pragma unroll
    for (int n = 0; n < 8; n++) {
        C1[n][0] = C1[n][0] * SCL + blo[n].x;
        C1[n][1] = C1[n][1] * SCL + blo[n].y;
        C1[n][2] = C1[n][2] * SCL + bhi[n].x;
        C1[n][3] = C1[n][3] * SCL + bhi[n].y;
        C2[n][0] = C2[n][0] * SCL + blo[n].x;
        C2[n][1] = C2[n][1] * SCL + blo[n].y;
        C2[n][2] = C2[n][2] * SCL + bhi[n].x;
        C2[n][3] = C2[n][3] * SCL + bhi[n].y;
    }

    // ---- dual softmax via ex2.approx, no max-subtraction (args bounded ~|9|) ----
    float s1l = 0.f, s1h = 0.f, s2l = 0.f, s2h = 0.f;
#pragma unroll
    for (int n = 0; n < 8; n++) {
        C1[n][0] = ex2(C1[n][0]); s1l += C1[n][0];
        C1[n][1] = ex2(C1[n][1]); s1l += C1[n][1];
        C1[n][2] = ex2(C1[n][2]); s1h += C1[n][2];
        C1[n][3] = ex2(C1[n][3]); s1h += C1[n][3];
        C2[n][0] = ex2(C2[n][0]); s2l += C2[n][0];
        C2[n][1] = ex2(C2[n][1]); s2l += C2[n][1];
        C2[n][2] = ex2(C2[n][2]); s2h += C2[n][2];
        C2[n][3] = ex2(C2[n][3]); s2h += C2[n][3];
    }
#pragma unroll
    for (int off = 1; off <= 2; off <<= 1) {
        s1l += __shfl_xor_sync(0xffffffffu, s1l, off);
        s1h += __shfl_xor_sync(0xffffffffu, s1h, off);
        s2l += __shfl_xor_sync(0xffffffffu, s2l, off);
        s2h += __shfl_xor_sync(0xffffffffu, s2h, off);
    }

    // mixed softmaxes each sum to 1 -> final renorm divides by exactly 1; skip.
    const float w1l = (1.0f - gv) / s1l, w1h = (1.0f - gv) / s1h;
    const float w2l = gv / s2l,          w2h = gv / s2h;

    // mixed attention -> warp-private rows of the aliased q1 tile (tf32 RNA).
#pragma unroll
    for (int n = 0; n < 8; n++) {
        float2 lo, hi;
        lo.x = tf32r(C1[n][0] * w1l + C2[n][0] * w2l);
        lo.y = tf32r(C1[n][1] * w1l + C2[n][1] * w2l);
        hi.x = tf32r(C1[n][2] * w1h + C2[n][2] * w2h);
        hi.y = tf32r(C1[n][3] * w1h + C2[n][3] * w2h);
        *(float2*)&ats[row_lo * SQ + n * 8 + 2 * qc] = lo;
        *(float2*)&ats[row_hi * SQ + n * 8 + 2 * qc] = hi;
    }

    // ---- v landed (latency hidden under all of QK+softmax) ----
    asm volatile("cp.async.wait_group 0;\n");
    __syncthreads();

    // ---- O = attn @ V (A via ldmatrix; v fed raw f32 -> HW tf32 truncation) ----
    float O[8][4];
#pragma unroll
    for (int n = 0; n < 8; n++)
#pragma unroll
        for (int j = 0; j < 4; j++) O[n][j] = 0.f;

    uint32_t adA = sb + (uint32_t)(OFF_Q1 + a_row * SQ) * 4u + a_coff;  // ats alias
#pragma unroll
    for (int kk = 0; kk < 8; kk++) {
        const int k0 = kk * 8;
        uint32_t AF[4];
        ldsm4(AF, adA);  adA += 32;   // already tf32 values
#pragma unroll
        for (int n = 0; n < 8; n++) {
            const int dcol = n * 8 + qg;
            uint32_t b0 = __float_as_uint(vs[(k0 + qc) * SV + dcol]);
            uint32_t b1 = __float_as_uint(vs[(k0 + qc + 4) * SV + dcol]);
            mma_tf32(O[n], AF[0], AF[1], AF[2], AF[3], b0, b1);
        }
    }

    // ---- store output: out[b, row, h*64 + d] ----
    float* op = outg + (size_t)b * NTOK * CDIM + (size_t)h * HD;
#pragma unroll
    for (int n = 0; n < 8; n++) {
        const int dcol = n * 8 + 2 * qc;
        *(float2*)&op[(size_t)row_lo * CDIM + dcol] = make_float2(O[n][0], O[n][1]);
        *(float2*)&op[(size_t)row_hi * CDIM + dcol] = make_float2(O[n][2], O[n][3]);
    }
}

extern "C" void kernel_launch(void* const* d_in, const int* in_sizes, int n_in,
                              void* d_out, int out_size) {
    const float* q1 = (const float*)d_in[0];
    const float* q2 = (const float*)d_in[1];
    const float* k1 = (const float*)d_in[2];
    const float* v1 = (const float*)d_in[3];
    // d_in[4] = k2 (unused by the reference math)
    const float* bias_table = (const float*)d_in[5];
    const float* gating     = (const float*)d_in[6];
    const int*   rel_index  = (const int*)d_in[7];
    float* out = (float*)d_out;

    const int smem_bytes = BUFF * (int)sizeof(float);  // 70656
    cudaFuncSetAttribute(win_attn_kernel,
                         cudaFuncAttributeMaxDynamicSharedMemorySize, smem_bytes);
    win_attn_kernel<<<NB * NH, 128, smem_bytes>>>(q1, q2, k1, v1,
                                                  bias_table, gating, rel_index, out);
}

// round 14
// speedup vs baseline: 1.2207x; 1.1370x over previous
#include <cuda_runtime.h>
#include <cstdint>

#define NB   2048
#define NTOK 64
#define CDIM 512
#define NH   8
#define HD   64

#define SQ 68   // smem row stride (floats) for q1/q2/k1/attn tiles
#define SV 72   // smem row stride (floats) for v tile

#define OFF_Q1 0
#define OFF_Q2 (NTOK * SQ)
#define OFF_K1 (2 * NTOK * SQ)
#define OFF_V  (3 * NTOK * SQ)
#define BUFF   (3 * NTOK * SQ + NTOK * SV)   // 17664 floats = 70656 B -> 3 CTAs/SM

// Precomputed bias[h][n][m] = bias_table[rel_index[n,m], h] * log2(e)
__device__ float g_bias[NH * NTOK * NTOK];

__global__ void bias_precompute(const float* __restrict__ bias_table,
                                const int* __restrict__ rel_index) {
    int i = blockIdx.x * blockDim.x + threadIdx.x;
    if (i < NTOK * NTOK) {
        int ri = rel_index[i];
#pragma unroll
        for (int h = 0; h < NH; h++)
            g_bias[h * (NTOK * NTOK) + i] = bias_table[ri * NH + h] * 1.4426950408889634f;
    }
}

__device__ __forceinline__ float ex2(float x) {
    float y;
    asm("ex2.approx.ftz.f32 %0, %1;" : "=f"(y) : "f"(x));
    return y;
}

__device__ __forceinline__ float tf32r(float x) {
    uint32_t u;
    asm("cvt.rna.tf32.f32 %0, %1;" : "=r"(u) : "f"(x));
    return __uint_as_float(u);
}
__device__ __forceinline__ uint32_t tf32b(uint32_t x) {
    uint32_t u;
    asm("cvt.rna.tf32.f32 %0, %1;" : "=r"(u) : "f"(__uint_as_float(x)));
    return u;
}

__device__ __forceinline__ void ldsm4(uint32_t r[4], uint32_t addr) {
    asm volatile("ldmatrix.sync.aligned.m8n8.x4.shared.b16 {%0,%1,%2,%3}, [%4];\n"
                 : "=r"(r[0]), "=r"(r[1]), "=r"(r[2]), "=r"(r[3]) : "r"(addr));
}

__device__ __forceinline__ void mma_tf32(float c[4],
                                         uint32_t a0, uint32_t a1, uint32_t a2, uint32_t a3,
                                         uint32_t b0, uint32_t b1) {
    asm volatile(
        "mma.sync.aligned.m16n8k8.row.col.f32.tf32.tf32.f32 "
        "{%0,%1,%2,%3}, {%4,%5,%6,%7}, {%8,%9}, {%0,%1,%2,%3};\n"
        : "+f"(c[0]), "+f"(c[1]), "+f"(c[2]), "+f"(c[3])
        : "r"(a0), "r"(a1), "r"(a2), "r"(a3), "r"(b0), "r"(b1));
}

__device__ __forceinline__ void cpa16(uint32_t s, const float* g) {
    asm volatile("cp.async.cg.shared.global [%0], [%1], 16;\n" :: "r"(s), "l"(g));
}

extern __shared__ float smem[];

__global__ __launch_bounds__(128)
void win_attn_kernel(const float* __restrict__ q1g,
                     const float* __restrict__ q2g,
                     const float* __restrict__ k1g,
                     const float* __restrict__ v1g,
                     const float* __restrict__ gating,
                     float* __restrict__ outg) {
    const int bh = blockIdx.x;
    const int b  = bh >> 3;
    const int h  = bh & 7;
    const int tid  = threadIdx.x;
    const int lane = tid & 31;
    const int warp = tid >> 5;
    const int qg = lane >> 2;   // group id (0..7)
    const int qc = lane & 3;    // thread-in-group (0..3)
    const uint32_t sb = (uint32_t)__cvta_generic_to_shared(smem);

    float* vs  = smem + OFF_V;
    float* ats = smem + OFF_Q1;   // q1 raw early; mixed attn later (warp-private rows)

    // ---- async stage: group 0 = q1+q2+k1 (QK path), group 1 = v (AV path) ----
    const size_t base = (size_t)b * NTOK * CDIM + (size_t)h * HD;
#pragma unroll
    for (int it = 0; it < 8; it++) {
        const int i  = tid + it * 128;
        const int r  = i >> 4;
        const int c4 = (i & 15) << 2;
        const size_t go = base + (size_t)r * CDIM + c4;
        cpa16(sb + (uint32_t)(OFF_Q1 + r * SQ + c4) * 4u, q1g + go);
        cpa16(sb + (uint32_t)(OFF_Q2 + r * SQ + c4) * 4u, q2g + go);
        cpa16(sb + (uint32_t)(OFF_K1 + r * SQ + c4) * 4u, k1g + go);
    }
    asm volatile("cp.async.commit_group;\n");
#pragma unroll
    for (int it = 0; it < 8; it++) {
        const int i  = tid + it * 128;
        const int r  = i >> 4;
        const int c4 = (i & 15) << 2;
        cpa16(sb + (uint32_t)(OFF_V + r * SV + c4) * 4u,
              v1g + base + (size_t)r * CDIM + c4);
    }
    asm volatile("cp.async.commit_group;\n");

    const int row_lo = warp * 16 + qg;
    const int row_hi = row_lo + 8;

    // ---- ldmatrix lane addressing (32-bit words via b16 tiles) ----
    const int a_row = warp * 16 + (lane & 15);
    const uint32_t a_coff = (uint32_t)((lane >> 4) << 4);           // 0 or 16 bytes
    uint32_t adQ1 = sb + (uint32_t)(OFF_Q1 + a_row * SQ) * 4u + a_coff;
    uint32_t adQ2 = sb + (uint32_t)(OFF_Q2 + a_row * SQ) * 4u + a_coff;
    const int b_row_in = ((lane >> 4) << 3) + (lane & 7);           // 0..15
    const uint32_t b_coff = (uint32_t)(((lane >> 3) & 1) << 4);     // 0 or 16 bytes
    uint32_t adB[4];
#pragma unroll
    for (int j = 0; j < 4; j++)
        adB[j] = sb + (uint32_t)(OFF_K1 + (16 * j + b_row_in) * SQ) * 4u + b_coff;

    // ---- bias + gating prefetch (dense L2-resident; hides under cp.async wait) ----
    float2 blo[8], bhi[8];
    {
        const float* bp_lo = g_bias + h * (NTOK * NTOK) + row_lo * NTOK + 2 * qc;
        const float* bp_hi = g_bias + h * (NTOK * NTOK) + row_hi * NTOK + 2 * qc;
#pragma unroll
        for (int n = 0; n < 8; n++) {
            blo[n] = *(const float2*)(bp_lo + n * 8);
            bhi[n] = *(const float2*)(bp_hi + n * 8);
        }
    }
    const float gp = __ldg(gating + h);
    const float gv = 1.0f / (1.0f + __expf(-gp));

    // ---- QK path operands landed ----
    asm volatile("cp.async.wait_group 1;\n");
    __syncthreads();

    // ---- QK^T for both maps (raw frags via ldmatrix, RNA-cvt in registers) ----
    float C1[8][4], C2[8][4];
#pragma unroll
    for (int n = 0; n < 8; n++)
#pragma unroll
        for (int j = 0; j < 4; j++) { C1[n][j] = 0.f; C2[n][j] = 0.f; }

#pragma unroll
    for (int kk = 0; kk < 8; kk++) {
        uint32_t A1[4], A2[4], B[4][4];
        ldsm4(A1, adQ1);  adQ1 += 32;
        ldsm4(A2, adQ2);  adQ2 += 32;
#pragma unroll
        for (int j = 0; j < 4; j++) { ldsm4(B[j], adB[j]); adB[j] += 32; }
#pragma unroll
        for (int i = 0; i < 4; i++) {
            A1[i] = tf32b(A1[i]);
            A2[i] = tf32b(A2[i]);
#pragma unroll
            for (int j = 0; j < 4; j++) B[j][i] = tf32b(B[j][i]);
        }
#pragma unroll
        for (int n = 0; n < 8; n++) {
            const uint32_t b0 = B[n >> 1][(n & 1) * 2];
            const uint32_t b1 = B[n >> 1][(n & 1) * 2 + 1];
            mma_tf32(C1[n], A1[0], A1[1], A1[2], A1[3], b0, b1);
            mma_tf32(C2[n], A2[0], A2[1], A2[2], A2[3], b0, b1);
        }
    }

    // ---- scale+bias in log2 domain: y = C*(0.125*log2e) + bias*log2e ----
    const float SCL = 0.18033688011112042f;  // 0.125 * log2(e)
#pragma unroll
    for (int n = 0; n < 8; n++) {
        C1[n][0] = C1[n][0] * SCL + blo[n].x;
        C1[n][1] = C1[n][1] * SCL + blo[n].y;
        C1[n][2] = C1[n][2] * SCL + bhi[n].x;
        C1[n][3] = C1[n][3] * SCL + bhi[n].y;
        C2[n][0] = C2[n][0] * SCL + blo[n].x;
        C2[n][1] = C2[n][1] * SCL + blo[n].y;
        C2[n][2] = C2[n][2] * SCL + bhi[n].x;
        C2[n][3] = C2[n][3] * SCL + bhi[n].y;
    }

    // ---- dual softmax via ex2.approx, no max-subtraction (args bounded ~|9|) ----
    float s1l = 0.f, s1h = 0.f, s2l = 0.f, s2h = 0.f;
#pragma unroll
    for (int n = 0; n < 8; n++) {
        C1[n][0] = ex2(C1[n][0]); s1l += C1[n][0];
        C1[n][1] = ex2(C1[n][1]); s1l += C1[n][1];
        C1[n][2] = ex2(C1[n][2]); s1h += C1[n][2];
        C1[n][3] = ex2(C1[n][3]); s1h += C1[n][3];
        C2[n][0] = ex2(C2[n][0]); s2l += C2[n][0];
        C2[n][1] = ex2(C2[n][1]); s2l += C2[n][1];
        C2[n][2] = ex2(C2[n][2]); s2h += C2[n][2];
        C2[n][3] = ex2(C2[n][3]); s2h += C2[n][3];
    }
#pragma unroll
    for (int off = 1; off <= 2; off <<= 1) {
        s1l += __shfl_xor_sync(0xffffffffu, s1l, off);
        s1h += __shfl_xor_sync(0xffffffffu, s1h, off);
        s2l += __shfl_xor_sync(0xffffffffu, s2l, off);
        s2h += __shfl_xor_sync(0xffffffffu, s2h, off);
    }

    // mixed softmaxes each sum to 1 -> final renorm divides by exactly 1; skip.
    const float w1l = (1.0f - gv) / s1l, w1h = (1.0f - gv) / s1h;
    const float w2l = gv / s2l,          w2h = gv / s2h;

    // mixed attention -> warp-private rows of the aliased q1 tile (tf32 RNA).
#pragma unroll
    for (int n = 0; n < 8; n++) {
        float2 lo, hi;
        lo.x = tf32r(C1[n][0] * w1l + C2[n][0] * w2l);
        lo.y = tf32r(C1[n][1] * w1l + C2[n][1] * w2l);
        hi.x = tf32r(C1[n][2] * w1h + C2[n][2] * w2h);
        hi.y = tf32r(C1[n][3] * w1h + C2[n][3] * w2h);
        *(float2*)&ats[row_lo * SQ + n * 8 + 2 * qc] = lo;
        *(float2*)&ats[row_hi * SQ + n * 8 + 2 * qc] = hi;
    }

    // ---- v landed (latency hidden under all of QK+softmax) ----
    asm volatile("cp.async.wait_group 0;\n");
    __syncthreads();

    // ---- O = attn @ V (A via ldmatrix; v fed raw f32 -> HW tf32 truncation) ----
    float O[8][4];
#pragma unroll
    for (int n = 0; n < 8; n++)
#pragma unroll
        for (int j = 0; j < 4; j++) O[n][j] = 0.f;

    uint32_t adA = sb + (uint32_t)(OFF_Q1 + a_row * SQ) * 4u + a_coff;  // ats alias
#pragma unroll
    for (int kk = 0; kk < 8; kk++) {
        const int k0 = kk * 8;
        uint32_t AF[4];
        ldsm4(AF, adA);  adA += 32;   // already tf32 values
#pragma unroll
        for (int n = 0; n < 8; n++) {
            const int dcol = n * 8 + qg;
            uint32_t b0 = __float_as_uint(vs[(k0 + qc) * SV + dcol]);
            uint32_t b1 = __float_as_uint(vs[(k0 + qc + 4) * SV + dcol]);
            mma_tf32(O[n], AF[0], AF[1], AF[2], AF[3], b0, b1);
        }
    }

    // ---- store output: out[b, row, h*64 + d] ----
    float* op = outg + (size_t)b * NTOK * CDIM + (size_t)h * HD;
#pragma unroll
    for (int n = 0; n < 8; n++) {
        const int dcol = n * 8 + 2 * qc;
        *(float2*)&op[(size_t)row_lo * CDIM + dcol] = make_float2(O[n][0], O[n][1]);
        *(float2*)&op[(size_t)row_hi * CDIM + dcol] = make_float2(O[n][2], O[n][3]);
    }
}

extern "C" void kernel_launch(void* const* d_in, const int* in_sizes, int n_in,
                              void* d_out, int out_size) {
    const float* q1 = (const float*)d_in[0];
    const float* q2 = (const float*)d_in[1];
    const float* k1 = (const float*)d_in[2];
    const float* v1 = (const float*)d_in[3];
    // d_in[4] = k2 (unused by the reference math)
    const float* bias_table = (const float*)d_in[5];
    const float* gating     = (const float*)d_in[6];
    const int*   rel_index  = (const int*)d_in[7];
    float* out = (float*)d_out;

    bias_precompute<<<16, 256>>>(bias_table, rel_index);

    const int smem_bytes = BUFF * (int)sizeof(float);  // 70656
    cudaFuncSetAttribute(win_attn_kernel,
                         cudaFuncAttributeMaxDynamicSharedMemorySize, smem_bytes);
    win_attn_kernel<<<NB * NH, 128, smem_bytes>>>(q1, q2, k1, v1, gating, out);
}